// round 6
// baseline (speedup 1.0000x reference)
#include <cuda_runtime.h>
#include <cuda_bf16.h>
#include <cstdint>

// VectorQuantizer: MMA bf16-split filter + exact fp32 rescue + output pass.
// z_e (64,64,64,64) f32, emb (512,64) f32.
// Output (f32): [ z_q : 16777216 ][ vq_loss : 1 ][ indices : 262144 ]

#define KCODES   512
#define DDIM     64
#define HW       4096
#define DHW      262144
#define NPTS     262144
#define LOSS_OFF 16777216
#define IDX_OFF  16777217

#define NCTAS    148
#define NTH      256
#define NWARPS   8
#define TOTWARPS (NCTAS * NWARPS)          // 1184
#define NPAIRS   (NPTS / 32)               // 8192 groups of 32 points

#define THRESH   2e-4f

// ---- pass-1 smem layout (bytes) ----
#define OFF_BHI   0                         // 65536
#define OFF_BLO   65536                     // 65536
#define OFF_ESQ   131072                    // 2048
#define OFF_ZSQ   133120                    // 8 warps * 32 * 4 = 1024
#define OFF_STAGE 134144                    // 8 warps * 8192 (hi 4096 | lo 4096)
#define SMEM1     199680

// ---- pass-3 smem layout ----
#define EROW      68
#define OFF3_RED  139264                    // 8 floats
#define OFF3_FIN  139304                    // 256 doubles (8-aligned)
#define SMEM3     141360

// XOR swizzle: row stride 128B, chunk = 16B
#define SWZ(row, c) (((row) * 128) + ((((c) ^ ((row) & 7))) << 4))

__device__ uint32_t g_bhi[16384];
__device__ uint32_t g_blo[16384];
__device__ float    g_esq[KCODES];
__device__ unsigned char g_flag[NPTS];
__device__ float    g_partials[1024];
__device__ int      g_counter = 0;

__device__ __forceinline__ uint32_t smem_u32(const void* p) {
    uint32_t a;
    asm("{ .reg .u64 t; cvta.to.shared.u64 t, %1; cvt.u32.u64 %0, t; }"
        : "=r"(a) : "l"(p));
    return a;
}
#define LDSM_X4(r0, r1, r2, r3, a) \
    asm volatile("ldmatrix.sync.aligned.m8n8.x4.shared.b16 {%0,%1,%2,%3}, [%4];" \
        : "=r"(r0), "=r"(r1), "=r"(r2), "=r"(r3) : "r"(a))

__device__ __forceinline__ void mma16816(float d[4], const uint32_t a[4],
                                         uint32_t b0, uint32_t b1) {
    asm volatile("mma.sync.aligned.m16n8k16.row.col.f32.bf16.bf16.f32 "
        "{%0,%1,%2,%3}, {%4,%5,%6,%7}, {%8,%9}, {%0,%1,%2,%3};"
        : "+f"(d[0]), "+f"(d[1]), "+f"(d[2]), "+f"(d[3])
        : "r"(a[0]), "r"(a[1]), "r"(a[2]), "r"(a[3]), "r"(b0), "r"(b1));
}

__device__ __forceinline__ void split2(float a, float b, uint32_t& hi, uint32_t& lo) {
    __nv_bfloat16 ah = __float2bfloat16(a);
    __nv_bfloat16 bh = __float2bfloat16(b);
    float ar = a - __bfloat162float(ah);
    float br = b - __bfloat162float(bh);
    __nv_bfloat162 h; h.x = ah; h.y = bh;
    __nv_bfloat162 l; l.x = __float2bfloat16(ar); l.y = __float2bfloat16(br);
    hi = *reinterpret_cast<uint32_t*>(&h);
    lo = *reinterpret_cast<uint32_t*>(&l);
}

// ---------------- prep: codebook -> swizzled bf16 hi/lo images + e_sq --------
extern "C" __global__ void vq_prep(const float* __restrict__ emb)
{
    int k = blockIdx.x * blockDim.x + threadIdx.x;
    if (k >= KCODES) return;
    const float* e = emb + k * DDIM;
    float v[DDIM];
    #pragma unroll
    for (int d = 0; d < DDIM; d++) v[d] = e[d];
    float s = 0.f;
    #pragma unroll
    for (int d = 0; d < DDIM; d++) s = fmaf(v[d], v[d], s);
    g_esq[k] = s;
    char* bh = (char*)g_bhi;
    char* bl = (char*)g_blo;
    #pragma unroll
    for (int c = 0; c < 8; c++) {
        uint32_t wh[4], wl[4];
        #pragma unroll
        for (int q = 0; q < 4; q++)
            split2(v[c * 8 + q * 2], v[c * 8 + q * 2 + 1], wh[q], wl[q]);
        int o = SWZ(k, c);
        *(uint4*)(bh + o) = make_uint4(wh[0], wh[1], wh[2], wh[3]);
        *(uint4*)(bl + o) = make_uint4(wl[0], wl[1], wl[2], wl[3]);
    }
}

// ---------------- pass 1: MMA filter (indices + ambiguity flags) -------------
extern "C" __global__ void __launch_bounds__(NTH, 1)
vq_main(const float* __restrict__ z, float* __restrict__ out)
{
    extern __shared__ char smem[];
    const int tid  = threadIdx.x;
    const int wib  = tid >> 5;
    const int lane = tid & 31;

    {
        const uint4* s1 = (const uint4*)g_bhi;
        const uint4* s2 = (const uint4*)g_blo;
        for (int i = tid; i < 4096; i += NTH) {
            *(uint4*)(smem + OFF_BHI + i * 16) = s1[i];
            *(uint4*)(smem + OFF_BLO + i * 16) = s2[i];
        }
        for (int k = tid; k < KCODES; k += NTH)
            *(float*)(smem + OFF_ESQ + k * 4) = g_esq[k];
    }
    __syncthreads();

    char* stageH = smem + OFF_STAGE + wib * 8192;
    char* stageL = stageH + 4096;
    float* zsq_s = (float*)(smem + OFF_ZSQ) + wib * 32;
    const float* esq_s = (const float*)(smem + OFF_ESQ);

    const uint32_t sH  = smem_u32(stageH);
    const uint32_t sL  = smem_u32(stageL);
    const uint32_t sBH = smem_u32(smem + OFF_BHI);
    const uint32_t sBL = smem_u32(smem + OFF_BLO);

    const int g    = lane >> 2;
    const int arow = (lane & 7) + (((lane >> 3) & 1) << 3);
    const int acs  = lane >> 4;
    const int brow = lane & 7;
    const int bcs  = lane >> 3;

    const int vw = wib * NCTAS + blockIdx.x;

    for (int tp = vw; tp < NPAIRS; tp += TOTWARPS) {
        const int p0  = tp * 32;
        const int n   = p0 >> 12;
        const int hw0 = p0 & (HW - 1);

        // ---- stage this lane's point (32 points / warp) ----
        {
            const float* zb = z + (size_t)n * DHW + hw0 + lane;
            float zsqp = 0.f;
            #pragma unroll
            for (int c = 0; c < 8; c++) {
                float v[8];
                #pragma unroll
                for (int j = 0; j < 8; j++) {
                    v[j] = zb[(size_t)(c * 8 + j) * HW];
                    zsqp = fmaf(v[j], v[j], zsqp);
                }
                uint32_t wh[4], wl[4];
                #pragma unroll
                for (int q = 0; q < 4; q++)
                    split2(v[q * 2], v[q * 2 + 1], wh[q], wl[q]);
                int o = SWZ(lane, c);
                *(uint4*)(stageH + o) = make_uint4(wh[0], wh[1], wh[2], wh[3]);
                *(uint4*)(stageL + o) = make_uint4(wl[0], wl[1], wl[2], wl[3]);
            }
            zsq_s[lane] = zsqp;
        }
        __syncwarp();

        // ---- A fragments for both 16-row tiles ----
        uint32_t Ah[2][16], Al[2][16];
        #pragma unroll
        for (int T = 0; T < 2; T++)
            #pragma unroll
            for (int kc = 0; kc < 4; kc++) {
                uint32_t ad = SWZ(T * 16 + arow, 2 * kc + acs);
                LDSM_X4(Ah[T][kc*4], Ah[T][kc*4+1], Ah[T][kc*4+2], Ah[T][kc*4+3],
                        sH + ad);
                LDSM_X4(Al[T][kc*4], Al[T][kc*4+1], Al[T][kc*4+2], Al[T][kc*4+3],
                        sL + ad);
            }

        const float zr[4] = { zsq_s[g], zsq_s[g + 8], zsq_s[g + 16], zsq_s[g + 24] };

        float bst[4] = {3.4e38f, 3.4e38f, 3.4e38f, 3.4e38f};
        float sec[4] = {3.4e38f, 3.4e38f, 3.4e38f, 3.4e38f};
        int   bix[4] = {0, 0, 0, 0};

        #pragma unroll 2
        for (int ch = 0; ch < 64; ch++) {
            const int n0 = ch * 8;
            uint32_t boff1 = (uint32_t)(n0 + brow) * 128 + (((bcs)     ^ brow) << 4);
            uint32_t boff2 = (uint32_t)(n0 + brow) * 128 + (((bcs + 4) ^ brow) << 4);
            uint32_t Bh[8], Bl[8];
            LDSM_X4(Bh[0], Bh[1], Bh[2], Bh[3], sBH + boff1);
            LDSM_X4(Bh[4], Bh[5], Bh[6], Bh[7], sBH + boff2);
            LDSM_X4(Bl[0], Bl[1], Bl[2], Bl[3], sBL + boff1);
            LDSM_X4(Bl[4], Bl[5], Bl[6], Bl[7], sBL + boff2);

            float d0[4] = {0.f, 0.f, 0.f, 0.f};
            float d1[4] = {0.f, 0.f, 0.f, 0.f};
            #pragma unroll
            for (int kc = 0; kc < 4; kc++) {
                mma16816(d0, Ah[0] + kc * 4, Bh[kc*2], Bh[kc*2+1]);
                mma16816(d0, Ah[0] + kc * 4, Bl[kc*2], Bl[kc*2+1]);
                mma16816(d0, Al[0] + kc * 4, Bh[kc*2], Bh[kc*2+1]);
                mma16816(d1, Ah[1] + kc * 4, Bh[kc*2], Bh[kc*2+1]);
                mma16816(d1, Ah[1] + kc * 4, Bl[kc*2], Bl[kc*2+1]);
                mma16816(d1, Al[1] + kc * 4, Bh[kc*2], Bh[kc*2+1]);
            }

            const int c0 = n0 + (lane & 3) * 2;
            const float e0 = esq_s[c0], e1 = esq_s[c0 + 1];
            const float* dd[4] = { d0, d0 + 2, d1, d1 + 2 };
            #pragma unroll
            for (int q = 0; q < 4; q++) {
                float dA = (zr[q] + e0) - (dd[q][0] + dd[q][0]);
                float dB = (zr[q] + e1) - (dd[q][1] + dd[q][1]);
                if (dA < bst[q]) { sec[q] = bst[q]; bst[q] = dA; bix[q] = c0; }
                else if (dA < sec[q]) sec[q] = dA;
                if (dB < bst[q]) { sec[q] = bst[q]; bst[q] = dB; bix[q] = c0 + 1; }
                else if (dB < sec[q]) sec[q] = dB;
            }
        }

        // ---- merge across the 4 lanes of each row group ----
        #pragma unroll
        for (int m = 1; m <= 2; m <<= 1) {
            #pragma unroll
            for (int q = 0; q < 4; q++) {
                float ob = __shfl_xor_sync(0xFFFFFFFFu, bst[q], m);
                int   oi = __shfl_xor_sync(0xFFFFFFFFu, bix[q], m);
                float os = __shfl_xor_sync(0xFFFFFFFFu, sec[q], m);
                float ns = fminf(fminf(sec[q], os), fmaxf(bst[q], ob));
                bool w = (ob < bst[q]) || (ob == bst[q] && oi < bix[q]);
                if (w) { bst[q] = ob; bix[q] = oi; }
                sec[q] = ns;
            }
        }

        if ((lane & 3) == 0) {
            const int rows[4] = { g, g + 8, g + 16, g + 24 };
            #pragma unroll
            for (int q = 0; q < 4; q++) {
                out[IDX_OFF + p0 + rows[q]] = (float)bix[q];
                g_flag[p0 + rows[q]] = (sec[q] - bst[q] < THRESH) ? 1 : 0;
            }
        }
        __syncwarp();
    }
}

// ---------------- pass 2: exact fp32 rescore of flagged points ---------------
extern "C" __global__ void __launch_bounds__(NTH, 1)
vq_rescore(const float* __restrict__ z, const float* __restrict__ emb,
           float* __restrict__ out)
{
    const int lane = threadIdx.x & 31;
    const int gw   = blockIdx.x * NWARPS + (threadIdx.x >> 5);

    for (int base = gw * 32; base < NPTS; base += TOTWARPS * 32) {
        unsigned f = g_flag[base + lane];
        unsigned mask = __ballot_sync(0xFFFFFFFFu, f != 0);
        while (mask) {
            int b = __ffs(mask) - 1;
            mask &= mask - 1;
            const int p  = base + b;
            const int n  = p >> 12;
            const int hw = p & (HW - 1);
            const float* zb = z + (size_t)n * DHW + hw;

            float zv[DDIM];
            float zsq = 0.f;
            #pragma unroll
            for (int d = 0; d < DDIM; d += 2) {
                float a = zb[(size_t)d * HW];
                float bb = zb[(size_t)(d + 1) * HW];
                zsq = fmaf(a, a, zsq);
                zsq = fmaf(bb, bb, zsq);
                zv[d] = a; zv[d + 1] = bb;
            }

            float best = 3.4e38f;
            int   bi   = 0;
            // lane handles codes k = j*32 + lane (ascending within lane)
            for (int j = 0; j < 16; j++) {
                const int k = j * 32 + lane;
                const float4* er = (const float4*)(emb + (size_t)k * DDIM);
                float esq = 0.f, c0 = 0.f, c1 = 0.f, c2 = 0.f, c3 = 0.f;
                #pragma unroll
                for (int q = 0; q < 16; q++) {
                    float4 ev = er[q];
                    esq = fmaf(ev.x, ev.x, esq);
                    esq = fmaf(ev.y, ev.y, esq);
                    esq = fmaf(ev.z, ev.z, esq);
                    esq = fmaf(ev.w, ev.w, esq);
                    c0 = fmaf(zv[q * 4],     ev.x, c0);
                    c1 = fmaf(zv[q * 4 + 1], ev.y, c1);
                    c2 = fmaf(zv[q * 4 + 2], ev.z, c2);
                    c3 = fmaf(zv[q * 4 + 3], ev.w, c3);
                }
                float dot = (c0 + c2) + (c1 + c3);     // R1 combine order
                float dist = fmaf(-2.0f, dot, zsq + esq);
                if (dist < best) { best = dist; bi = k; }
            }
            #pragma unroll
            for (int off = 16; off > 0; off >>= 1) {
                float ob = __shfl_down_sync(0xFFFFFFFFu, best, off);
                int   oi = __shfl_down_sync(0xFFFFFFFFu, bi,   off);
                if (ob < best || (ob == best && oi < bi)) { best = ob; bi = oi; }
            }
            if (lane == 0) out[IDX_OFF + p] = (float)bi;
        }
    }
}

// ---------------- pass 3: z_q gather (exact fp32), loss, finalize ------------
extern "C" __global__ void __launch_bounds__(NTH, 1)
vq_output(const float* __restrict__ z, const float* __restrict__ emb,
          float* __restrict__ out)
{
    extern __shared__ char smem[];
    float*  se   = (float*)smem;                   // KCODES * EROW
    float*  sred = (float*)(smem + OFF3_RED);
    double* sdbl = (double*)(smem + OFF3_FIN);

    const int tid  = threadIdx.x;
    const int wib  = tid >> 5;
    const int lane = tid & 31;

    {
        const float4* e4 = (const float4*)emb;     // 8192 float4
        for (int i = tid; i < 8192; i += NTH) {
            int k = i >> 4, j = i & 15;
            *(float4*)(se + k * EROW + 4 * j) = e4[i];
        }
    }
    __syncthreads();

    const int p  = blockIdx.x * NTH + tid;
    const int n  = p >> 12;
    const int hw = p & (HW - 1);
    const int bidx = (int)out[IDX_OFF + p];
    const float* zb = z + (size_t)n * DHW + hw;
    const float* eb = se + bidx * EROW;
    float* op = out + (size_t)n * DHW + hw;

    float ls = 0.f;
    #pragma unroll
    for (int d = 0; d < DDIM; d += 2) {
        float a  = zb[(size_t)d * HW];
        float b  = zb[(size_t)(d + 1) * HW];
        float v0 = eb[d];
        float v1 = eb[d + 1];
        op[(size_t)d * HW]       = v0;
        op[(size_t)(d + 1) * HW] = v1;
        float d0 = a - v0, d1 = b - v1;
        ls = fmaf(d0, d0, ls);
        ls = fmaf(d1, d1, ls);
    }

    #pragma unroll
    for (int off = 16; off > 0; off >>= 1)
        ls += __shfl_down_sync(0xFFFFFFFFu, ls, off);
    if (lane == 0) sred[wib] = ls;
    __syncthreads();
    if (tid == 0) {
        float s = 0.f;
        #pragma unroll
        for (int w = 0; w < NWARPS; w++) s += sred[w];
        g_partials[blockIdx.x] = s;
        __threadfence();
        int prev = atomicAdd(&g_counter, 1);
        sred[0] = (prev == 1023) ? 1.f : 0.f;
    }
    __syncthreads();
    if (sred[0] != 0.f) {
        double v = ((double)g_partials[tid] + (double)g_partials[tid + 256])
                 + ((double)g_partials[tid + 512] + (double)g_partials[tid + 768]);
        sdbl[tid] = v;
        __syncthreads();
        #pragma unroll
        for (int off = 128; off > 0; off >>= 1) {
            if (tid < off) sdbl[tid] += sdbl[tid + off];
            __syncthreads();
        }
        if (tid == 0) {
            out[LOSS_OFF] = (float)(sdbl[0] / 16777216.0);
            g_counter = 0;   // graph-replay safe
        }
    }
}

extern "C" void kernel_launch(void* const* d_in, const int* in_sizes, int n_in,
                              void* d_out, int out_size)
{
    const float* z   = (const float*)d_in[0];
    const float* emb = (const float*)d_in[1];
    if (n_in >= 2 && in_sizes[0] < in_sizes[1]) {
        const float* t = z; z = emb; emb = t;
    }
    float* out = (float*)d_out;

    static bool attr_set = false;
    if (!attr_set) {
        cudaFuncSetAttribute(vq_main, cudaFuncAttributeMaxDynamicSharedMemorySize,
                             SMEM1);
        cudaFuncSetAttribute(vq_output, cudaFuncAttributeMaxDynamicSharedMemorySize,
                             SMEM3);
        attr_set = true;
    }

    vq_prep<<<4, 128>>>(emb);
    vq_main<<<NCTAS, NTH, SMEM1>>>(z, out);
    vq_rescore<<<NCTAS, NTH>>>(z, emb, out);
    vq_output<<<1024, NTH, SMEM3>>>(z, emb, out);
}

// round 8
// speedup vs baseline: 1.2362x; 1.2362x over previous
#include <cuda_runtime.h>
#include <cstdint>

// VectorQuantizer: int8 dp4a filter + candidate-exact rescue.
// z_e (64,64,64,64) f32, emb (512,64) f32.
// Output (f32): [ z_q : 16777216 ][ vq_loss : 1 ][ indices : 262144 ]

#define KCODES   512
#define DDIM     64
#define HW       4096
#define DHW      262144
#define NPTS     262144
#define LOSS_OFF 16777216
#define IDX_OFF  16777217

#define NCTAS    148
#define NTH1     512
#define NW1      16
#define TOTW1    (NCTAS * NW1)      // 2368
#define NTILES   (NPTS / 64)        // 4096 warp-tiles of 64 points
#define NTH2     256
#define NW2      8
#define TOTW2    (NCTAS * NW2)      // 1184
#define NGRP     (NPTS / 32)        // 8192

#define THRESH   1.0e-3f
#define MARGIN   2.5e-3f
#define SE       65024.0f           // 127*512 (|e| < 1/512 -> |e*SE| < 127)
#define EROW     68                 // padded fp32 codebook row (floats)

// ---- pass1 smem (bytes) ----
#define OFF_E8   0                  // 32768 : int8 codebook (16 u32 / code)
#define OFF_ESQ  32768              // 2048
#define OFF_RED  34816              // 64
#define OFF_EF   34944              // 512*68*4 = 139264 : fp32 padded codebook
#define SMEM1    174208

__device__ uint4         g_e8[KCODES * 4];
__device__ float         g_esq[KCODES];
__device__ unsigned char g_flag[NPTS];
__device__ float         g_p1[NCTAS];
__device__ float         g_p2[NCTAS];

__device__ __forceinline__ uint32_t pack4(int i0, int i1, int i2, int i3) {
    return __byte_perm(__byte_perm((uint32_t)i0, (uint32_t)i1, 0x0040),
                       __byte_perm((uint32_t)i2, (uint32_t)i3, 0x0040), 0x5410);
}

// ---------------- prep: int8 codebook + e_sq ----------------
extern "C" __global__ void vq_prep(const float* __restrict__ emb)
{
    int k = blockIdx.x * blockDim.x + threadIdx.x;
    if (k >= KCODES) return;
    const float* e = emb + k * DDIM;
    float s = 0.f;
    #pragma unroll
    for (int d = 0; d < DDIM; d++) s = fmaf(e[d], e[d], s);
    g_esq[k] = s;
    #pragma unroll
    for (int c = 0; c < 4; c++) {
        uint32_t w[4];
        #pragma unroll
        for (int q = 0; q < 4; q++) {
            int b = (c * 4 + q) * 4;
            w[q] = pack4(__float2int_rn(e[b]     * SE),
                         __float2int_rn(e[b + 1] * SE),
                         __float2int_rn(e[b + 2] * SE),
                         __float2int_rn(e[b + 3] * SE));
        }
        g_e8[k * 4 + c] = make_uint4(w[0], w[1], w[2], w[3]);
    }
}

// quantize one point (strided z) to 16 packed int8 words + filter scale
__device__ __forceinline__ void quant_pt(const float* __restrict__ zb,
                                         uint32_t q[16], float& cneg)
{
    float mx = 0.f;
    #pragma unroll
    for (int d = 0; d < DDIM; d++)
        mx = fmaxf(mx, fabsf(zb[(size_t)d * HW]));
    mx = fmaxf(mx, 1e-30f);
    float sz = 127.f / mx;
    #pragma unroll
    for (int c = 0; c < 16; c++) {
        int b = c * 4;
        q[c] = pack4(__float2int_rn(zb[(size_t)(b)     * HW] * sz),
                     __float2int_rn(zb[(size_t)(b + 1) * HW] * sz),
                     __float2int_rn(zb[(size_t)(b + 2) * HW] * sz),
                     __float2int_rn(zb[(size_t)(b + 3) * HW] * sz));
    }
    cneg = -2.f * mx / (127.f * SE);
}

// write z_q + index + flag, return loss contribution (0 if flagged)
__device__ __forceinline__ float emit_pt(float* __restrict__ out,
                                         const float* __restrict__ zb,
                                         const float* __restrict__ sEF,
                                         int n, int hw, int p, int idx, int flag)
{
    const float4* eb = (const float4*)(sEF + idx * EROW);
    float* op = out + (size_t)n * DHW + hw;
    float acc = 0.f;
    #pragma unroll
    for (int j = 0; j < 16; j++) {
        float4 ev = eb[j];
        int d = j * 4;
        float a0 = zb[(size_t)(d)     * HW];
        float a1 = zb[(size_t)(d + 1) * HW];
        float a2 = zb[(size_t)(d + 2) * HW];
        float a3 = zb[(size_t)(d + 3) * HW];
        op[(size_t)(d)     * HW] = ev.x;
        op[(size_t)(d + 1) * HW] = ev.y;
        op[(size_t)(d + 2) * HW] = ev.z;
        op[(size_t)(d + 3) * HW] = ev.w;
        float d0 = a0 - ev.x, d1 = a1 - ev.y, d2 = a2 - ev.z, d3 = a3 - ev.w;
        acc = fmaf(d0, d0, acc); acc = fmaf(d1, d1, acc);
        acc = fmaf(d2, d2, acc); acc = fmaf(d3, d3, acc);
    }
    out[IDX_OFF + p] = (float)idx;
    g_flag[p] = (unsigned char)flag;
    return flag ? 0.f : acc;
}

// ---------------- pass 1: dp4a filter + fused outputs ----------------
extern "C" __global__ void __launch_bounds__(NTH1, 1)
vq_pass1(const float* __restrict__ z, const float* __restrict__ emb,
         float* __restrict__ out)
{
    extern __shared__ char sm[];
    uint4* sB   = (uint4*)(sm + OFF_E8);
    float* sesq = (float*)(sm + OFF_ESQ);
    float* sred = (float*)(sm + OFF_RED);
    float* sEF  = (float*)(sm + OFF_EF);

    const int tid = threadIdx.x, wib = tid >> 5, lane = tid & 31;

    for (int i = tid; i < KCODES * 4; i += NTH1) sB[i] = g_e8[i];
    for (int k = tid; k < KCODES; k += NTH1)     sesq[k] = g_esq[k];
    {
        const float4* e4 = (const float4*)emb;
        for (int i = tid; i < KCODES * 16; i += NTH1) {
            int k = i >> 4, j = i & 15;
            *(float4*)(sEF + k * EROW + 4 * j) = e4[i];
        }
    }
    __syncthreads();

    float ls = 0.f;
    const int vw = wib * NCTAS + blockIdx.x;

    for (int t = vw; t < NTILES; t += TOTW1) {
        const int p0 = t * 64 + lane;
        const int n  = p0 >> 12;
        const int hw = p0 & (HW - 1);
        const float* zb0 = z + (size_t)n * DHW + hw;
        const float* zb1 = zb0 + 32;

        uint32_t q0[16], q1[16];
        float cn0, cn1;
        quant_pt(zb0, q0, cn0);
        quant_pt(zb1, q1, cn1);

        float b0 = 3.4e38f, s0 = 3.4e38f, b1 = 3.4e38f, s1 = 3.4e38f;
        int   i0 = 0, i1 = 0;
        for (int k = 0; k < KCODES; k++) {
            uint32_t B[16];
            *(uint4*)(B)      = sB[k * 4];
            *(uint4*)(B + 4)  = sB[k * 4 + 1];
            *(uint4*)(B + 8)  = sB[k * 4 + 2];
            *(uint4*)(B + 12) = sB[k * 4 + 3];
            int a0 = 0, a1 = 0, a2 = 0, a3 = 0;
            #pragma unroll
            for (int c = 0; c < 8; c++) {
                a0 = __dp4a((int)q0[c], (int)B[c], a0);
                a2 = __dp4a((int)q1[c], (int)B[c], a2);
            }
            #pragma unroll
            for (int c = 8; c < 16; c++) {
                a1 = __dp4a((int)q0[c], (int)B[c], a1);
                a3 = __dp4a((int)q1[c], (int)B[c], a3);
            }
            float e  = sesq[k];
            float f0 = fmaf(cn0, __int2float_rn(a0 + a1), e);
            float f1 = fmaf(cn1, __int2float_rn(a2 + a3), e);
            bool m0 = f0 < b0;
            s0 = fminf(s0, m0 ? b0 : f0);  b0 = m0 ? f0 : b0;  i0 = m0 ? k : i0;
            bool m1 = f1 < b1;
            s1 = fminf(s1, m1 ? b1 : f1);  b1 = m1 ? f1 : b1;  i1 = m1 ? k : i1;
        }
        int fl0 = (s0 - b0) < THRESH;
        int fl1 = (s1 - b1) < THRESH;

        ls += emit_pt(out, zb0, sEF, n, hw,      p0,      i0, fl0);
        ls += emit_pt(out, zb1, sEF, n, hw + 32, p0 + 32, i1, fl1);
    }

    #pragma unroll
    for (int off = 16; off > 0; off >>= 1)
        ls += __shfl_down_sync(0xFFFFFFFFu, ls, off);
    if (lane == 0) sred[wib] = ls;
    __syncthreads();
    if (tid == 0) {
        float s = 0.f;
        #pragma unroll
        for (int w = 0; w < NW1; w++) s += sred[w];
        g_p1[blockIdx.x] = s;
    }
}

// ---------------- pass 2: flagged points -> candidate exact rescore ----------
extern "C" __global__ void __launch_bounds__(NTH2, 1)
vq_fix(const float* __restrict__ z, const float* __restrict__ emb,
       float* __restrict__ out)
{
    __shared__ uint4 sB[KCODES * 4];
    __shared__ float sesq[KCODES];
    __shared__ float sred[NW2];

    const int tid = threadIdx.x, wib = tid >> 5, lane = tid & 31;
    for (int i = tid; i < KCODES * 4; i += NTH2) sB[i] = g_e8[i];
    for (int k = tid; k < KCODES; k += NTH2)     sesq[k] = g_esq[k];
    __syncthreads();

    float wls = 0.f;
    const int gw = wib * NCTAS + blockIdx.x;

    for (int g = gw; g < NGRP; g += TOTW2) {
        const int pb = g * 32;
        unsigned mask = __ballot_sync(0xFFFFFFFFu, g_flag[pb + lane] != 0);
        while (mask) {
            int b = __ffs(mask) - 1;
            mask &= mask - 1;
            const int p  = pb + b;
            const int n  = p >> 12;
            const int hw = p & (HW - 1);
            const float* zb = z + (size_t)n * DHW + hw;

            // z values + zsq (proven exact chain), per-point quantization
            float zv[DDIM];
            float zsq = 0.f;
            #pragma unroll
            for (int d = 0; d < DDIM; d += 2) {
                float a = zb[(size_t)d * HW];
                float bb = zb[(size_t)(d + 1) * HW];
                zsq = fmaf(a, a, zsq);
                zsq = fmaf(bb, bb, zsq);
                zv[d] = a; zv[d + 1] = bb;
            }
            float mx = 0.f;
            #pragma unroll
            for (int d = 0; d < DDIM; d++) mx = fmaxf(mx, fabsf(zv[d]));
            mx = fmaxf(mx, 1e-30f);
            float sz = 127.f / mx;
            uint32_t q[16];
            #pragma unroll
            for (int c = 0; c < 16; c++) {
                int d = c * 4;
                q[c] = pack4(__float2int_rn(zv[d]     * sz),
                             __float2int_rn(zv[d + 1] * sz),
                             __float2int_rn(zv[d + 2] * sz),
                             __float2int_rn(zv[d + 3] * sz));
            }
            float cn = -2.f * mx / (127.f * SE);

            // re-filter: lane handles codes k = j*32 + lane
            float fv[16], fmin = 3.4e38f;
            #pragma unroll
            for (int j = 0; j < 16; j++) {
                const int k = j * 32 + lane;
                uint32_t B[16];
                *(uint4*)(B)      = sB[k * 4];
                *(uint4*)(B + 4)  = sB[k * 4 + 1];
                *(uint4*)(B + 8)  = sB[k * 4 + 2];
                *(uint4*)(B + 12) = sB[k * 4 + 3];
                int a0 = 0, a1 = 0;
                #pragma unroll
                for (int c = 0; c < 8; c++)  a0 = __dp4a((int)q[c], (int)B[c], a0);
                #pragma unroll
                for (int c = 8; c < 16; c++) a1 = __dp4a((int)q[c], (int)B[c], a1);
                float f = fmaf(cn, __int2float_rn(a0 + a1), sesq[k]);
                fv[j] = f;
                fmin = fminf(fmin, f);
            }
            #pragma unroll
            for (int off = 16; off > 0; off >>= 1)
                fmin = fminf(fmin, __shfl_xor_sync(0xFFFFFFFFu, fmin, off));

            // exact-score candidate codes only
            float dbest = 3.4e38f;
            int   kbest = KCODES;
            const float thr = fmin + MARGIN;
            #pragma unroll
            for (int j = 0; j < 16; j++) {
                if (fv[j] <= thr) {
                    const int k = j * 32 + lane;
                    const float4* er = (const float4*)(emb + (size_t)k * DDIM);
                    float esq = 0.f, c0 = 0.f, c1 = 0.f, c2 = 0.f, c3 = 0.f;
                    #pragma unroll
                    for (int qq = 0; qq < 16; qq++) {
                        float4 ev = er[qq];
                        esq = fmaf(ev.x, ev.x, esq);
                        esq = fmaf(ev.y, ev.y, esq);
                        esq = fmaf(ev.z, ev.z, esq);
                        esq = fmaf(ev.w, ev.w, esq);
                        c0 = fmaf(zv[qq * 4],     ev.x, c0);
                        c1 = fmaf(zv[qq * 4 + 1], ev.y, c1);
                        c2 = fmaf(zv[qq * 4 + 2], ev.z, c2);
                        c3 = fmaf(zv[qq * 4 + 3], ev.w, c3);
                    }
                    float dot  = (c0 + c2) + (c1 + c3);
                    float dist = fmaf(-2.0f, dot, zsq + esq);
                    if (dist < dbest) { dbest = dist; kbest = k; }
                }
            }
            #pragma unroll
            for (int off = 16; off > 0; off >>= 1) {
                float od = __shfl_down_sync(0xFFFFFFFFu, dbest, off);
                int   oi = __shfl_down_sync(0xFFFFFFFFu, kbest, off);
                if (od < dbest || (od == dbest && oi < kbest)) { dbest = od; kbest = oi; }
            }
            kbest = __shfl_sync(0xFFFFFFFFu, kbest, 0);

            const int kold = (int)out[IDX_OFF + p];
            float e0 = emb[(size_t)kbest * DDIM + lane];
            float e1 = emb[(size_t)kbest * DDIM + lane + 32];
            float* op = out + (size_t)n * DHW + hw;
            if (kbest != kold) {
                if (lane == 0) out[IDX_OFF + p] = (float)kbest;
                op[(size_t)lane * HW]        = e0;
                op[(size_t)(lane + 32) * HW] = e1;
            }
            float d0 = zv[lane] - e0, d1 = zv[lane + 32] - e1;
            wls = fmaf(d0, d0, wls);
            wls = fmaf(d1, d1, wls);
        }
    }

    #pragma unroll
    for (int off = 16; off > 0; off >>= 1)
        wls += __shfl_down_sync(0xFFFFFFFFu, wls, off);
    if (lane == 0) sred[wib] = wls;
    __syncthreads();
    if (tid == 0) {
        float s = 0.f;
        #pragma unroll
        for (int w = 0; w < NW2; w++) s += sred[w];
        g_p2[blockIdx.x] = s;
    }
}

// ---------------- finalize loss ----------------
extern "C" __global__ void vq_fin(float* __restrict__ out)
{
    __shared__ double sd[256];
    const int tid = threadIdx.x;
    double v = 0.0;
    if (tid < NCTAS) v = (double)g_p1[tid] + (double)g_p2[tid];
    sd[tid] = v;
    __syncthreads();
    #pragma unroll
    for (int off = 128; off > 0; off >>= 1) {
        if (tid < off) sd[tid] += sd[tid + off];
        __syncthreads();
    }
    if (tid == 0) out[LOSS_OFF] = (float)(sd[0] / 16777216.0);
}

extern "C" void kernel_launch(void* const* d_in, const int* in_sizes, int n_in,
                              void* d_out, int out_size)
{
    const float* z   = (const float*)d_in[0];
    const float* emb = (const float*)d_in[1];
    if (n_in >= 2 && in_sizes[0] < in_sizes[1]) {
        const float* t = z; z = emb; emb = t;
    }
    float* out = (float*)d_out;

    static bool attr_set = false;
    if (!attr_set) {
        cudaFuncSetAttribute(vq_pass1, cudaFuncAttributeMaxDynamicSharedMemorySize,
                             SMEM1);
        attr_set = true;
    }

    vq_prep<<<4, 128>>>(emb);
    vq_pass1<<<NCTAS, NTH1, SMEM1>>>(z, emb, out);
    vq_fix<<<NCTAS, NTH2>>>(z, emb, out);
    vq_fin<<<1, 256>>>(out);
}

// round 10
// speedup vs baseline: 1.6170x; 1.3080x over previous
#include <cuda_runtime.h>
#include <cstdint>

// VectorQuantizer: exact fp32 FFMA2 register-blocked GEMM + fused argmin.
// z_e (64,64,64,64) f32, emb (512,64) f32.
// Output (f32): [ z_q : 16777216 ][ vq_loss : 1 ][ indices : 262144 ]

#define KCODES   512
#define DDIM     64
#define HW       4096
#define DHW      262144
#define NPTS     262144
#define LOSS_OFF 16777216
#define IDX_OFF  16777217

#define NCTAS    148
#define NTH      512
#define TILE_P   64
#define NTILES   (NPTS / TILE_P)        // 4096

// ---- smem layout (bytes) ----
#define OFF_E    0                       // f32 [64 d][512 k] = 131072
#define OFF_ESQ  131072                  // 512 f32
#define OFF_Z    133120                  // 2 bufs × f32 [64 d][64 pt] = 2*16384
#define OFF_PZ   165888                  // 8 × 64 f32 partial zsq
#define OFF_ZSQ  167936                  // 2 × 64 f32
#define OFF_BDD  168448                  // 16 warps × 8 f32  (warp best dist)
#define OFF_BDI  168960                  // 16 warps × 8 int  (warp best idx)
#define OFF_BI   169472                  // 64 int
#define OFF_RED  169728                  // 16 f32
#define OFF_FLAG 169792
#define OFF_FIN  169800                  // 256 doubles (8-aligned)
#define SMEM_SZ  171904

__device__ float g_partials[NCTAS];
__device__ int   g_counter = 0;

__device__ __forceinline__ uint64_t pk2(float lo, float hi) {
    uint64_t r;
    asm("mov.b64 %0, {%1, %2};" : "=l"(r) : "f"(lo), "f"(hi));
    return r;
}
__device__ __forceinline__ float2 upk2(uint64_t v) {
    float2 r;
    asm("mov.b64 {%0, %1}, %2;" : "=f"(r.x), "=f"(r.y) : "l"(v));
    return r;
}
__device__ __forceinline__ void ffma2(uint64_t& d, uint64_t a, uint64_t b) {
    asm("fma.rn.f32x2 %0, %1, %2, %0;" : "+l"(d) : "l"(a), "l"(b));
}

extern "C" __global__ void __launch_bounds__(NTH, 1)
vq_kernel(const float* __restrict__ z, const float* __restrict__ emb,
          float* __restrict__ out)
{
    extern __shared__ char sm[];
    float*  sEf   = (float*)(sm + OFF_E);      // [d][k]
    float*  sesq  = (float*)(sm + OFF_ESQ);
    float*  sZf   = (float*)(sm + OFF_Z);      // [buf][d][pt]
    float*  sPZ   = (float*)(sm + OFF_PZ);     // [g][pt]
    float*  sZSQ  = (float*)(sm + OFF_ZSQ);    // [buf][pt]
    float*  sBDD  = (float*)(sm + OFF_BDD);    // [warp][j]
    int*    sBDI  = (int*)  (sm + OFF_BDI);
    int*    sBI   = (int*)  (sm + OFF_BI);
    float*  sred  = (float*)(sm + OFF_RED);
    int*    sflag = (int*)  (sm + OFF_FLAG);
    double* sdbl  = (double*)(sm + OFF_FIN);

    const int tid  = threadIdx.x;
    const int wib  = tid >> 5;
    const int lane = tid & 31;
    const int tk   = tid & 63;    // code group: codes tk*8 .. tk*8+7
    const int tp   = tid >> 6;    // pt group:  pts   tp*8 .. tp*8+7

    // ---- codebook -> smem transposed [d][k] ----
    for (int i = tid; i < KCODES * DDIM; i += NTH) {
        int k = i >> 6, d = i & 63;
        sEf[d * KCODES + k] = emb[i];
    }
    // ---- e_sq (from gmem, L2-hot) ----
    for (int k = tid; k < KCODES; k += NTH) {
        const float* e = emb + (size_t)k * DDIM;
        float s = 0.f;
        #pragma unroll
        for (int d = 0; d < DDIM; d++) s = fmaf(e[d], e[d], s);
        sesq[k] = s;
    }
    __syncthreads();

    // this thread's 8 esq values (constant for the whole kernel)
    float esqr[8];
    #pragma unroll
    for (int c = 0; c < 8; c++) esqr[c] = sesq[tk * 8 + c];

    const char* se8 = (const char*)sEf;
    float lsum = 0.f;
    int buf = 0;
    const int t0 = blockIdx.x;

    // ---- stage first tile into buf 0 ----
    if (t0 < NTILES) {
        const int n0  = t0 >> 6;
        const int hw0 = (t0 & 63) * 64;
        float psq = 0.f;
        #pragma unroll
        for (int i2 = 0; i2 < 8; i2++) {
            int d = tp + 8 * i2;
            float v = z[(size_t)n0 * DHW + (size_t)d * HW + hw0 + tk];
            sZf[d * 64 + tk] = v;
            psq = fmaf(v, v, psq);
        }
        sPZ[tp * 64 + tk] = psq;
    }
    __syncthreads();
    if (tid < 64) {
        float s = 0.f;
        #pragma unroll
        for (int g2 = 0; g2 < 8; g2++) s += sPZ[g2 * 64 + tid];
        sZSQ[tid] = s;
    }
    __syncthreads();

    for (int t = t0; t < NTILES; t += NCTAS) {
        const int tn = t + NCTAS;
        const bool pf = (tn < NTILES);

        // ---- prefetch next tile's z into registers (overlaps compute) ----
        float r[8];
        if (pf) {
            const int n2  = tn >> 6;
            const int hw2 = (tn & 63) * 64;
            #pragma unroll
            for (int i2 = 0; i2 < 8; i2++) {
                int d = tp + 8 * i2;
                r[i2] = z[(size_t)n2 * DHW + (size_t)d * HW + hw2 + tk];
            }
        }

        // ---- main GEMM fragment: 8 pts x 8 codes (4 code-pair accums/pt) ----
        uint64_t acc[32];
        #pragma unroll
        for (int i2 = 0; i2 < 32; i2++) acc[i2] = 0ull;

        const float* zc = sZf + buf * 4096;
        #pragma unroll 4
        for (int d = 0; d < DDIM; d++) {
            float4 za = *(const float4*)(zc + d * 64 + tp * 8);
            float4 zb = *(const float4*)(zc + d * 64 + tp * 8 + 4);
            ulonglong2 e01 = *(const ulonglong2*)(se8 + (size_t)d * 2048 + tk * 32);
            ulonglong2 e23 = *(const ulonglong2*)(se8 + (size_t)d * 2048 + tk * 32 + 16);
            uint64_t zz[8];
            zz[0] = pk2(za.x, za.x); zz[1] = pk2(za.y, za.y);
            zz[2] = pk2(za.z, za.z); zz[3] = pk2(za.w, za.w);
            zz[4] = pk2(zb.x, zb.x); zz[5] = pk2(zb.y, zb.y);
            zz[6] = pk2(zb.z, zb.z); zz[7] = pk2(zb.w, zb.w);
            #pragma unroll
            for (int j = 0; j < 8; j++) {
                ffma2(acc[j * 4 + 0], zz[j], e01.x);
                ffma2(acc[j * 4 + 1], zz[j], e01.y);
                ffma2(acc[j * 4 + 2], zz[j], e23.x);
                ffma2(acc[j * 4 + 3], zz[j], e23.y);
            }
        }

        // ---- fused argmin epilogue ----
        #pragma unroll
        for (int j = 0; j < 8; j++) {
            float zsqv = sZSQ[buf * 64 + tp * 8 + j];
            float bb = 3.4e38f;
            int   bi = 0;
            #pragma unroll
            for (int cp = 0; cp < 4; cp++) {
                float2 dots = upk2(acc[j * 4 + cp]);
                int k0 = tk * 8 + cp * 2;
                float d0 = fmaf(-2.0f, dots.x, zsqv + esqr[cp * 2]);
                float d1 = fmaf(-2.0f, dots.y, zsqv + esqr[cp * 2 + 1]);
                if (d0 < bb) { bb = d0; bi = k0; }
                if (d1 < bb) { bb = d1; bi = k0 + 1; }
            }
            #pragma unroll
            for (int off = 16; off > 0; off >>= 1) {
                float ob = __shfl_down_sync(0xFFFFFFFFu, bb, off);
                int   oi = __shfl_down_sync(0xFFFFFFFFu, bi, off);
                if (ob < bb || (ob == bb && oi < bi)) { bb = ob; bi = oi; }
            }
            if (lane == 0) { sBDD[wib * 8 + j] = bb; sBDI[wib * 8 + j] = bi; }
        }
        __syncthreads();

        if (tid < 64) {
            const int tpg = tid >> 3, j = tid & 7;
            const int w0 = tpg * 2, w1 = w0 + 1;
            float dA = sBDD[w0 * 8 + j], dB = sBDD[w1 * 8 + j];
            int   iA = sBDI[w0 * 8 + j], iB = sBDI[w1 * 8 + j];
            int win = (dB < dA) ? iB : iA;   // tie -> lower codes (half A)
            sBI[tid] = win;
            out[IDX_OFF + t * TILE_P + tid] = (float)win;
        }
        __syncthreads();

        // ---- outputs: z_q gather (exact fp32), loss ----
        {
            const int n1  = t >> 6;
            const int hw1 = (t & 63) * 64;
            #pragma unroll
            for (int i2 = 0; i2 < 8; i2++) {
                int d = tp + 8 * i2;
                int k = sBI[tk];
                float ev = sEf[d * KCODES + k];
                float zv = zc[d * 64 + tk];
                out[(size_t)n1 * DHW + (size_t)d * HW + hw1 + tk] = ev;
                float df = zv - ev;
                lsum = fmaf(df, df, lsum);
            }
        }

        // ---- stage next tile (regs -> other buffer) ----
        if (pf) {
            float* zn = sZf + (buf ^ 1) * 4096;
            float psq = 0.f;
            #pragma unroll
            for (int i2 = 0; i2 < 8; i2++) {
                int d = tp + 8 * i2;
                zn[d * 64 + tk] = r[i2];
                psq = fmaf(r[i2], r[i2], psq);
            }
            sPZ[tp * 64 + tk] = psq;
        }
        __syncthreads();
        if (pf && tid < 64) {
            float s = 0.f;
            #pragma unroll
            for (int g2 = 0; g2 < 8; g2++) s += sPZ[g2 * 64 + tid];
            sZSQ[(buf ^ 1) * 64 + tid] = s;
        }
        __syncthreads();
        if (pf) buf ^= 1;
    }

    // ---- loss reduction (deterministic) ----
    #pragma unroll
    for (int off = 16; off > 0; off >>= 1)
        lsum += __shfl_down_sync(0xFFFFFFFFu, lsum, off);
    if (lane == 0) sred[wib] = lsum;
    __syncthreads();
    if (tid == 0) {
        float s = 0.f;
        #pragma unroll
        for (int w = 0; w < 16; w++) s += sred[w];
        g_partials[blockIdx.x] = s;
        __threadfence();
        int prev = atomicAdd(&g_counter, 1);
        *sflag = (prev == NCTAS - 1);
    }
    __syncthreads();

    if (*sflag) {
        if (tid < 256) {
            double v = 0.0;
            if (tid < NCTAS) v = (double)g_partials[tid];
            sdbl[tid] = v;
        }
        __syncthreads();
        #pragma unroll
        for (int off = 128; off > 0; off >>= 1) {
            if (tid < off) sdbl[tid] += sdbl[tid + off];
            __syncthreads();
        }
        if (tid == 0) {
            out[LOSS_OFF] = (float)(sdbl[0] / 16777216.0);
            g_counter = 0;   // graph-replay safe
        }
    }
}

extern "C" void kernel_launch(void* const* d_in, const int* in_sizes, int n_in,
                              void* d_out, int out_size)
{
    const float* z   = (const float*)d_in[0];
    const float* emb = (const float*)d_in[1];
    if (n_in >= 2 && in_sizes[0] < in_sizes[1]) {
        const float* t = z; z = emb; emb = t;
    }
    float* out = (float*)d_out;

    static bool attr_set = false;
    if (!attr_set) {
        cudaFuncSetAttribute(vq_kernel, cudaFuncAttributeMaxDynamicSharedMemorySize,
                             SMEM_SZ);
        attr_set = true;
    }

    vq_kernel<<<NCTAS, NTH, SMEM_SZ>>>(z, emb, out);
}